// round 16
// baseline (speedup 1.0000x reference)
#include <cuda_runtime.h>
#include <cstdint>

// Problem constants (match reference)
#define NV   100000
#define NE   20000
#define DD   64
#define ALPHA 0.5f
#define BETA  0.5f

#define MAXNNZ 1000000
#define CAP     128
#define CAPSH   7

// ---------------------------------------------------------------------------
// Scratch (__device__ globals only)
// ---------------------------------------------------------------------------
__device__ __align__(16) float g_Xv[NV * DD];
__device__ int g_cur[NE];
__device__ int g_perm[NE * CAP];

// ---------------------------------------------------------------------------
// Kernel 1: zero cursors
// ---------------------------------------------------------------------------
__global__ void zero_cur() {
    int i = blockIdx.x * blockDim.x + threadIdx.x;
    if (i < NE) g_cur[i] = 0;
}

// ---------------------------------------------------------------------------
// Kernel 2: zero Xv (fused) + fill fixed-capacity buckets
// ---------------------------------------------------------------------------
__global__ __launch_bounds__(512) void fill_e(const int* __restrict__ vertex,
                                              const int* __restrict__ edges, int nnz) {
    const int gt = blockIdx.x * blockDim.x + threadIdx.x;
    const int T  = gridDim.x * blockDim.x;

    const int n4v = NV * DD / 4;
    float4 z = make_float4(0.f, 0.f, 0.f, 0.f);
    for (int i = gt; i < n4v; i += T)
        reinterpret_cast<float4*>(g_Xv)[i] = z;

    int i = gt * 8;
    if (i + 7 < nnz) {
        int4 e0 = __ldg((const int4*)(edges + i));
        int4 e1 = __ldg((const int4*)(edges + i + 4));
        int4 v0 = __ldg((const int4*)(vertex + i));
        int4 v1 = __ldg((const int4*)(vertex + i + 4));
        int p0 = atomicAdd(&g_cur[e0.x], 1);
        int p1 = atomicAdd(&g_cur[e0.y], 1);
        int p2 = atomicAdd(&g_cur[e0.z], 1);
        int p3 = atomicAdd(&g_cur[e0.w], 1);
        int p4 = atomicAdd(&g_cur[e1.x], 1);
        int p5 = atomicAdd(&g_cur[e1.y], 1);
        int p6 = atomicAdd(&g_cur[e1.z], 1);
        int p7 = atomicAdd(&g_cur[e1.w], 1);
        g_perm[(e0.x << CAPSH) + p0] = v0.x;
        g_perm[(e0.y << CAPSH) + p1] = v0.y;
        g_perm[(e0.z << CAPSH) + p2] = v0.z;
        g_perm[(e0.w << CAPSH) + p3] = v0.w;
        g_perm[(e1.x << CAPSH) + p4] = v1.x;
        g_perm[(e1.y << CAPSH) + p5] = v1.y;
        g_perm[(e1.z << CAPSH) + p6] = v1.z;
        g_perm[(e1.w << CAPSH) + p7] = v1.w;
    } else {
        for (; i < nnz; ++i) {
            int e = __ldg(edges + i);
            int v = __ldg(vertex + i);
            int p = atomicAdd(&g_cur[e], 1);
            g_perm[(e << CAPSH) + p] = v;
        }
    }
}

// ---------------------------------------------------------------------------
// red.global.add.v4.f32
// ---------------------------------------------------------------------------
__device__ __forceinline__ void red_add_v4(float* dst, float4 v) {
    asm volatile("red.global.add.v4.f32 [%0], {%1, %2, %3, %4};"
                 :: "l"(dst), "f"(v.x), "f"(v.y), "f"(v.z), "f"(v.w)
                 : "memory");
}

__device__ __forceinline__ void f4acc(float4& a, float4 x) {
    a.x += x.x; a.y += x.y; a.z += x.z; a.w += x.w;
}

// ---------------------------------------------------------------------------
// Kernel 3: FUSED edge-major pass
// ---------------------------------------------------------------------------
__global__ __launch_bounds__(256) void fused_edge_pass(const float* __restrict__ X) {
    int t = blockIdx.x * blockDim.x + threadIdx.x;
    int b = t >> 4;
    if (b >= NE) return;
    int c = (t & 15) << 2;
    int start = b << CAPSH;
    int deg   = __ldg(g_cur + b);

    float4 a0 = make_float4(0.f, 0.f, 0.f, 0.f);
    float4 a1 = a0, a2 = a0, a3 = a0;
    int j = 0;
    for (; j + 4 <= deg; j += 4) {
        int i0 = __ldg(g_perm + start + j);
        int i1 = __ldg(g_perm + start + j + 1);
        int i2 = __ldg(g_perm + start + j + 2);
        int i3 = __ldg(g_perm + start + j + 3);
        f4acc(a0, *reinterpret_cast<const float4*>(X + (size_t)i0 * DD + c));
        f4acc(a1, *reinterpret_cast<const float4*>(X + (size_t)i1 * DD + c));
        f4acc(a2, *reinterpret_cast<const float4*>(X + (size_t)i2 * DD + c));
        f4acc(a3, *reinterpret_cast<const float4*>(X + (size_t)i3 * DD + c));
    }
    for (; j < deg; ++j) {
        int i0 = __ldg(g_perm + start + j);
        f4acc(a0, *reinterpret_cast<const float4*>(X + (size_t)i0 * DD + c));
    }
    float4 acc;
    acc.x = (a0.x + a1.x) + (a2.x + a3.x);
    acc.y = (a0.y + a1.y) + (a2.y + a3.y);
    acc.z = (a0.z + a1.z) + (a2.z + a3.z);
    acc.w = (a0.w + a1.w) + (a2.w + a3.w);

    j = 0;
    for (; j + 4 <= deg; j += 4) {
        int i0 = __ldg(g_perm + start + j);
        int i1 = __ldg(g_perm + start + j + 1);
        int i2 = __ldg(g_perm + start + j + 2);
        int i3 = __ldg(g_perm + start + j + 3);
        red_add_v4(g_Xv + (size_t)i0 * DD + c, acc);
        red_add_v4(g_Xv + (size_t)i1 * DD + c, acc);
        red_add_v4(g_Xv + (size_t)i2 * DD + c, acc);
        red_add_v4(g_Xv + (size_t)i3 * DD + c, acc);
    }
    for (; j < deg; ++j) {
        int i0 = __ldg(g_perm + start + j);
        red_add_v4(g_Xv + (size_t)i0 * DD + c, acc);
    }
}

// ---------------------------------------------------------------------------
// f32x2 helpers
// ---------------------------------------------------------------------------
__device__ __forceinline__ uint64_t pack2(float lo, float hi) {
    uint64_t r;
    asm("mov.b64 %0, {%1, %2};" : "=l"(r) : "f"(lo), "f"(hi));
    return r;
}
__device__ __forceinline__ void ffma2(uint64_t& d, uint64_t a, uint64_t b) {
    asm("fma.rn.f32x2 %0, %1, %2, %3;" : "=l"(d) : "l"(a), "l"(b), "l"(d));
}
__device__ __forceinline__ float2 unpack2(uint64_t v) {
    float lo, hi;
    asm("mov.b64 {%0, %1}, %2;" : "=f"(lo), "=f"(hi) : "l"(v));
    return make_float2(lo, hi);
}

// ---------------------------------------------------------------------------
// Kernel 4: epilogue. 64-row tiles, 256 threads, thread = 4 rows x 4 cols.
// K-packed FFMA2 with 128-bit shared loads:
//   A: LDS.128 = 4 consecutive k of one row (broadcast across 16 lanes)
//   B: LDS.128 = WtQ[c][kq] -> (kp-even u64, kp-odd u64)
// Per kq: 8 LDS.128 + 32 FFMA2 (halved LDS instruction count vs LDS.64).
// rows: tr + 16i, cols: tc + 16j.
// ---------------------------------------------------------------------------
#define MTILE 64
#define PADK  68      // S/H pitch in floats (272 B, 16B-aligned rows)
#define WQP   34      // WtQ pitch in u64 (272 B rows, 16B-aligned)

__global__ __launch_bounds__(256) void epilogue(
        const float* __restrict__ X0,
        const float* __restrict__ W1, const float* __restrict__ b1,
        const float* __restrict__ W2, const float* __restrict__ b2,
        float* __restrict__ out) {
    __shared__ float    S[MTILE * PADK];        // 17408 B  Xi
    __shared__ float    H[MTILE * PADK];        // 17408 B  h
    __shared__ uint64_t WtQ1[64 * WQP];         // 17408 B
    __shared__ uint64_t WtQ2[64 * WQP];         // 17408 B
    __shared__ float    bs1[64];

    const int tid  = threadIdx.x;
    const int tc   = tid & 15;
    const int tr   = tid >> 4;
    const int base = blockIdx.x * MTILE;

    // Pack weights: WtQ[c*WQP + 2*kq]   = (W[4kq][c],   W[4kq+1][c])
    //               WtQ[c*WQP + 2*kq+1] = (W[4kq+2][c], W[4kq+3][c])
    #pragma unroll
    for (int idx = tid; idx < 64 * 16; idx += 256) {
        int c  = idx & 63;
        int kq = idx >> 6;
        int k4 = kq << 2;
        WtQ1[c * WQP + 2 * kq]     = pack2(__ldg(W1 + (k4    ) * 64 + c),
                                           __ldg(W1 + (k4 + 1) * 64 + c));
        WtQ1[c * WQP + 2 * kq + 1] = pack2(__ldg(W1 + (k4 + 2) * 64 + c),
                                           __ldg(W1 + (k4 + 3) * 64 + c));
        WtQ2[c * WQP + 2 * kq]     = pack2(__ldg(W2 + (k4    ) * 64 + c),
                                           __ldg(W2 + (k4 + 1) * 64 + c));
        WtQ2[c * WQP + 2 * kq + 1] = pack2(__ldg(W2 + (k4 + 2) * 64 + c),
                                           __ldg(W2 + (k4 + 3) * 64 + c));
    }
    if (tid < 64) bs1[tid] = b1[tid];
    float b2r[4];
    #pragma unroll
    for (int j = 0; j < 4; ++j) b2r[j] = __ldg(b2 + tc + 16 * j);

    // Xi = (1-A)*Xv + A*X0 into S
    #pragma unroll
    for (int idx = tid; idx < MTILE * 16; idx += 256) {
        int r = idx >> 4, q = (idx & 15) << 2;
        int row = base + r;
        float4 xi = make_float4(0.f, 0.f, 0.f, 0.f);
        if (row < NV) {
            float4 xv = __ldg((const float4*)(g_Xv + (size_t)row * DD + q));
            float4 x0 = __ldg((const float4*)(X0   + (size_t)row * DD + q));
            xi.x = (1.f - ALPHA) * xv.x + ALPHA * x0.x;
            xi.y = (1.f - ALPHA) * xv.y + ALPHA * x0.y;
            xi.z = (1.f - ALPHA) * xv.z + ALPHA * x0.z;
            xi.w = (1.f - ALPHA) * xv.w + ALPHA * x0.w;
        }
        *(float4*)(S + r * PADK + q) = xi;
    }
    __syncthreads();

    // GEMM 1: rows tr+16i, cols tc+16j
    uint64_t acc[4][4];
    #pragma unroll
    for (int i = 0; i < 4; ++i)
        #pragma unroll
        for (int j = 0; j < 4; ++j) acc[i][j] = 0ull;

    #pragma unroll 4
    for (int kq = 0; kq < 16; ++kq) {
        uint4 bq0 = *(const uint4*)(WtQ1 + (tc     ) * WQP + 2 * kq);
        uint4 bq1 = *(const uint4*)(WtQ1 + (tc + 16) * WQP + 2 * kq);
        uint4 bq2 = *(const uint4*)(WtQ1 + (tc + 32) * WQP + 2 * kq);
        uint4 bq3 = *(const uint4*)(WtQ1 + (tc + 48) * WQP + 2 * kq);
        uint64_t b0e = ((uint64_t)bq0.y << 32) | bq0.x, b0o = ((uint64_t)bq0.w << 32) | bq0.z;
        uint64_t b1e = ((uint64_t)bq1.y << 32) | bq1.x, b1o = ((uint64_t)bq1.w << 32) | bq1.z;
        uint64_t b2e = ((uint64_t)bq2.y << 32) | bq2.x, b2o = ((uint64_t)bq2.w << 32) | bq2.z;
        uint64_t b3e = ((uint64_t)bq3.y << 32) | bq3.x, b3o = ((uint64_t)bq3.w << 32) | bq3.z;
        #pragma unroll
        for (int i = 0; i < 4; ++i) {
            uint4 av = *(const uint4*)(S + (tr + 16 * i) * PADK + 4 * kq);
            uint64_t a01 = ((uint64_t)av.y << 32) | av.x;
            uint64_t a23 = ((uint64_t)av.w << 32) | av.z;
            ffma2(acc[i][0], a01, b0e); ffma2(acc[i][0], a23, b0o);
            ffma2(acc[i][1], a01, b1e); ffma2(acc[i][1], a23, b1o);
            ffma2(acc[i][2], a01, b2e); ffma2(acc[i][2], a23, b2o);
            ffma2(acc[i][3], a01, b3e); ffma2(acc[i][3], a23, b3o);
        }
    }

    // h = relu(lo+hi + b1) into H
    #pragma unroll
    for (int i = 0; i < 4; ++i) {
        int r = tr + 16 * i;
        #pragma unroll
        for (int j = 0; j < 4; ++j) {
            int c = tc + 16 * j;
            float2 p = unpack2(acc[i][j]);
            H[r * PADK + c] = fmaxf(p.x + p.y + bs1[c], 0.f);
        }
    }
    __syncthreads();

    // GEMM 2
    #pragma unroll
    for (int i = 0; i < 4; ++i)
        #pragma unroll
        for (int j = 0; j < 4; ++j) acc[i][j] = 0ull;

    #pragma unroll 4
    for (int kq = 0; kq < 16; ++kq) {
        uint4 bq0 = *(const uint4*)(WtQ2 + (tc     ) * WQP + 2 * kq);
        uint4 bq1 = *(const uint4*)(WtQ2 + (tc + 16) * WQP + 2 * kq);
        uint4 bq2 = *(const uint4*)(WtQ2 + (tc + 32) * WQP + 2 * kq);
        uint4 bq3 = *(const uint4*)(WtQ2 + (tc + 48) * WQP + 2 * kq);
        uint64_t b0e = ((uint64_t)bq0.y << 32) | bq0.x, b0o = ((uint64_t)bq0.w << 32) | bq0.z;
        uint64_t b1e = ((uint64_t)bq1.y << 32) | bq1.x, b1o = ((uint64_t)bq1.w << 32) | bq1.z;
        uint64_t b2e = ((uint64_t)bq2.y << 32) | bq2.x, b2o = ((uint64_t)bq2.w << 32) | bq2.z;
        uint64_t b3e = ((uint64_t)bq3.y << 32) | bq3.x, b3o = ((uint64_t)bq3.w << 32) | bq3.z;
        #pragma unroll
        for (int i = 0; i < 4; ++i) {
            uint4 av = *(const uint4*)(H + (tr + 16 * i) * PADK + 4 * kq);
            uint64_t a01 = ((uint64_t)av.y << 32) | av.x;
            uint64_t a23 = ((uint64_t)av.w << 32) | av.z;
            ffma2(acc[i][0], a01, b0e); ffma2(acc[i][0], a23, b0o);
            ffma2(acc[i][1], a01, b1e); ffma2(acc[i][1], a23, b1o);
            ffma2(acc[i][2], a01, b2e); ffma2(acc[i][2], a23, b2o);
            ffma2(acc[i][3], a01, b3e); ffma2(acc[i][3], a23, b3o);
        }
    }

    // out = (1-BETA)*Xi + BETA*(acc + b2); Xi from S (still valid)
    #pragma unroll
    for (int i = 0; i < 4; ++i) {
        int row = base + tr + 16 * i;
        if (row < NV) {
            #pragma unroll
            for (int j = 0; j < 4; ++j) {
                int c = tc + 16 * j;
                float2 p = unpack2(acc[i][j]);
                float xiv = S[(tr + 16 * i) * PADK + c];
                out[(size_t)row * DD + c] =
                    (1.f - BETA) * xiv + BETA * (p.x + p.y + b2r[j]);
            }
        }
    }
}

// ---------------------------------------------------------------------------
extern "C" void kernel_launch(void* const* d_in, const int* in_sizes, int n_in,
                              void* d_out, int out_size) {
    const float* X      = (const float*)d_in[0];
    const float* X0     = (const float*)d_in[1];
    const float* W1     = (const float*)d_in[2];
    const float* b1     = (const float*)d_in[3];
    const float* W2     = (const float*)d_in[4];
    const float* b2     = (const float*)d_in[5];
    const int*   vertex = (const int*)d_in[6];
    const int*   edges  = (const int*)d_in[7];
    float*       out    = (float*)d_out;

    const int nnz = in_sizes[6];
    const int n8  = (nnz + 7) / 8;

    zero_cur<<<(NE + 255) / 256, 256>>>();
    fill_e<<<(n8 + 511) / 512, 512>>>(vertex, edges, nnz);
    fused_edge_pass<<<(NE * 16 + 255) / 256, 256>>>(X);
    epilogue<<<(NV + MTILE - 1) / MTILE, 256>>>(X0, W1, b1, W2, b2, out);
}

// round 17
// speedup vs baseline: 1.1691x; 1.1691x over previous
#include <cuda_runtime.h>
#include <cstdint>

// Problem constants (match reference)
#define NV   100000
#define NE   20000
#define DD   64
#define ALPHA 0.5f
#define BETA  0.5f

#define MAXNNZ 1000000
#define CAP     128
#define CAPSH   7

// ---------------------------------------------------------------------------
// Scratch (__device__ globals only)
// g_cur padded: one cursor per 128-byte L2 line -> contended atomics don't
// serialize on shared lines.
// ---------------------------------------------------------------------------
__device__ __align__(16) float g_Xv[NV * DD];
__device__ int g_cur[NE * 32];            // cursor at e*32
__device__ int g_perm[NE * CAP];

// ---------------------------------------------------------------------------
// Kernel 1: zero cursors (one per line)
// ---------------------------------------------------------------------------
__global__ void zero_cur() {
    int i = blockIdx.x * blockDim.x + threadIdx.x;
    if (i < NE) g_cur[i << 5] = 0;
}

// ---------------------------------------------------------------------------
// Kernel 2: zero Xv (fused) + fill fixed-capacity buckets (4 entries/thread)
// ---------------------------------------------------------------------------
__global__ __launch_bounds__(512) void fill_e(const int* __restrict__ vertex,
                                              const int* __restrict__ edges, int nnz) {
    const int gt = blockIdx.x * blockDim.x + threadIdx.x;
    const int T  = gridDim.x * blockDim.x;

    const int n4v = NV * DD / 4;
    float4 z = make_float4(0.f, 0.f, 0.f, 0.f);
    for (int i = gt; i < n4v; i += T)
        reinterpret_cast<float4*>(g_Xv)[i] = z;

    int i = gt * 4;
    if (i + 3 < nnz) {
        int4 e = __ldg((const int4*)(edges + i));
        int4 v = __ldg((const int4*)(vertex + i));
        int p0 = atomicAdd(&g_cur[e.x << 5], 1);
        int p1 = atomicAdd(&g_cur[e.y << 5], 1);
        int p2 = atomicAdd(&g_cur[e.z << 5], 1);
        int p3 = atomicAdd(&g_cur[e.w << 5], 1);
        g_perm[(e.x << CAPSH) + p0] = v.x;
        g_perm[(e.y << CAPSH) + p1] = v.y;
        g_perm[(e.z << CAPSH) + p2] = v.z;
        g_perm[(e.w << CAPSH) + p3] = v.w;
    } else {
        for (; i < nnz; ++i) {
            int e = __ldg(edges + i);
            int v = __ldg(vertex + i);
            int p = atomicAdd(&g_cur[e << 5], 1);
            g_perm[(e << CAPSH) + p] = v;
        }
    }
}

// ---------------------------------------------------------------------------
// red.global.add.v4.f32
// ---------------------------------------------------------------------------
__device__ __forceinline__ void red_add_v4(float* dst, float4 v) {
    asm volatile("red.global.add.v4.f32 [%0], {%1, %2, %3, %4};"
                 :: "l"(dst), "f"(v.x), "f"(v.y), "f"(v.z), "f"(v.w)
                 : "memory");
}

__device__ __forceinline__ void f4acc(float4& a, float4 x) {
    a.x += x.x; a.y += x.y; a.z += x.z; a.w += x.w;
}

// ---------------------------------------------------------------------------
// Kernel 3: FUSED edge-major pass
// ---------------------------------------------------------------------------
__global__ __launch_bounds__(256) void fused_edge_pass(const float* __restrict__ X) {
    int t = blockIdx.x * blockDim.x + threadIdx.x;
    int b = t >> 4;
    if (b >= NE) return;
    int c = (t & 15) << 2;
    int start = b << CAPSH;
    int deg   = __ldg(g_cur + (b << 5));

    float4 a0 = make_float4(0.f, 0.f, 0.f, 0.f);
    float4 a1 = a0, a2 = a0, a3 = a0;
    int j = 0;
    for (; j + 4 <= deg; j += 4) {
        int i0 = __ldg(g_perm + start + j);
        int i1 = __ldg(g_perm + start + j + 1);
        int i2 = __ldg(g_perm + start + j + 2);
        int i3 = __ldg(g_perm + start + j + 3);
        f4acc(a0, *reinterpret_cast<const float4*>(X + (size_t)i0 * DD + c));
        f4acc(a1, *reinterpret_cast<const float4*>(X + (size_t)i1 * DD + c));
        f4acc(a2, *reinterpret_cast<const float4*>(X + (size_t)i2 * DD + c));
        f4acc(a3, *reinterpret_cast<const float4*>(X + (size_t)i3 * DD + c));
    }
    for (; j < deg; ++j) {
        int i0 = __ldg(g_perm + start + j);
        f4acc(a0, *reinterpret_cast<const float4*>(X + (size_t)i0 * DD + c));
    }
    float4 acc;
    acc.x = (a0.x + a1.x) + (a2.x + a3.x);
    acc.y = (a0.y + a1.y) + (a2.y + a3.y);
    acc.z = (a0.z + a1.z) + (a2.z + a3.z);
    acc.w = (a0.w + a1.w) + (a2.w + a3.w);

    j = 0;
    for (; j + 4 <= deg; j += 4) {
        int i0 = __ldg(g_perm + start + j);
        int i1 = __ldg(g_perm + start + j + 1);
        int i2 = __ldg(g_perm + start + j + 2);
        int i3 = __ldg(g_perm + start + j + 3);
        red_add_v4(g_Xv + (size_t)i0 * DD + c, acc);
        red_add_v4(g_Xv + (size_t)i1 * DD + c, acc);
        red_add_v4(g_Xv + (size_t)i2 * DD + c, acc);
        red_add_v4(g_Xv + (size_t)i3 * DD + c, acc);
    }
    for (; j < deg; ++j) {
        int i0 = __ldg(g_perm + start + j);
        red_add_v4(g_Xv + (size_t)i0 * DD + c, acc);
    }
}

// ---------------------------------------------------------------------------
// f32x2 helpers
// ---------------------------------------------------------------------------
__device__ __forceinline__ uint64_t pack2(float lo, float hi) {
    uint64_t r;
    asm("mov.b64 %0, {%1, %2};" : "=l"(r) : "f"(lo), "f"(hi));
    return r;
}
__device__ __forceinline__ void ffma2(uint64_t& d, uint64_t a, uint64_t b) {
    asm("fma.rn.f32x2 %0, %1, %2, %3;" : "=l"(d) : "l"(a), "l"(b), "l"(d));
}
__device__ __forceinline__ float2 unpack2(uint64_t v) {
    float lo, hi;
    asm("mov.b64 {%0, %1}, %2;" : "=f"(lo), "=f"(hi) : "l"(v));
    return make_float2(lo, hi);
}

// ---------------------------------------------------------------------------
// Kernel 4: epilogue (R14 structure, conflict-free WPAIR=33), forced to
// 4 blocks/SM for 50% occupancy. 64-row tiles, 256 threads, 4x4 per thread,
// K-packed FFMA2 (acc.lo even-k, acc.hi odd-k).
// rows: tr + 16i, cols: tc + 16j.
// ---------------------------------------------------------------------------
#define MTILE 64
#define PADK  68      // S/H pitch (floats)
#define WPAIR 33      // Wt pitch (u64) -> bank stride 2 per tc: conflict-free

__global__ __launch_bounds__(256, 4) void epilogue(
        const float* __restrict__ X0,
        const float* __restrict__ W1, const float* __restrict__ b1,
        const float* __restrict__ W2, const float* __restrict__ b2,
        float* __restrict__ out) {
    __shared__ float    S[MTILE * PADK];       // 17408 B  Xi
    __shared__ float    H[MTILE * PADK];       // 17408 B  h
    __shared__ uint64_t Wt1[64 * WPAIR];       // 16896 B
    __shared__ uint64_t Wt2b[64 * WPAIR];      // 16896 B
    __shared__ float    bs1[64];

    const int tid  = threadIdx.x;
    const int tc   = tid & 15;
    const int tr   = tid >> 4;
    const int base = blockIdx.x * MTILE;

    // Pack both weight matrices (coalesced: idx = kp*64 + c)
    #pragma unroll
    for (int idx = tid; idx < 64 * 32; idx += 256) {
        int c  = idx & 63;
        int kp = idx >> 6;
        Wt1[c * WPAIR + kp]  = pack2(__ldg(W1 + (2 * kp) * 64 + c),
                                     __ldg(W1 + (2 * kp + 1) * 64 + c));
        Wt2b[c * WPAIR + kp] = pack2(__ldg(W2 + (2 * kp) * 64 + c),
                                     __ldg(W2 + (2 * kp + 1) * 64 + c));
    }
    if (tid < 64) bs1[tid] = b1[tid];

    // Xi = (1-A)*Xv + A*X0 into S
    #pragma unroll
    for (int idx = tid; idx < MTILE * 16; idx += 256) {
        int r = idx >> 4, q = (idx & 15) << 2;
        int row = base + r;
        float4 xi = make_float4(0.f, 0.f, 0.f, 0.f);
        if (row < NV) {
            float4 xv = __ldg((const float4*)(g_Xv + (size_t)row * DD + q));
            float4 x0 = __ldg((const float4*)(X0   + (size_t)row * DD + q));
            xi.x = (1.f - ALPHA) * xv.x + ALPHA * x0.x;
            xi.y = (1.f - ALPHA) * xv.y + ALPHA * x0.y;
            xi.z = (1.f - ALPHA) * xv.z + ALPHA * x0.z;
            xi.w = (1.f - ALPHA) * xv.w + ALPHA * x0.w;
        }
        *(float4*)(S + r * PADK + q) = xi;
    }
    __syncthreads();

    // GEMM 1: acc[i][j], rows tr+16i, cols tc+16j
    uint64_t acc[4][4];
    #pragma unroll
    for (int i = 0; i < 4; ++i)
        #pragma unroll
        for (int j = 0; j < 4; ++j) acc[i][j] = 0ull;

    #pragma unroll 8
    for (int kp = 0; kp < 32; ++kp) {
        int k2 = kp << 1;
        uint64_t bq0 = Wt1[(tc     ) * WPAIR + kp];
        uint64_t bq1 = Wt1[(tc + 16) * WPAIR + kp];
        uint64_t bq2 = Wt1[(tc + 32) * WPAIR + kp];
        uint64_t bq3 = Wt1[(tc + 48) * WPAIR + kp];
        #pragma unroll
        for (int i = 0; i < 4; ++i) {
            uint64_t a = *(const uint64_t*)(S + (tr + 16 * i) * PADK + k2);
            ffma2(acc[i][0], a, bq0);
            ffma2(acc[i][1], a, bq1);
            ffma2(acc[i][2], a, bq2);
            ffma2(acc[i][3], a, bq3);
        }
    }

    // h = relu(lo+hi + b1) into H (separate buffer: no hazard on S)
    #pragma unroll
    for (int i = 0; i < 4; ++i) {
        int r = tr + 16 * i;
        #pragma unroll
        for (int j = 0; j < 4; ++j) {
            int c = tc + 16 * j;
            float2 p = unpack2(acc[i][j]);
            H[r * PADK + c] = fmaxf(p.x + p.y + bs1[c], 0.f);
        }
    }
    __syncthreads();

    // GEMM 2
    #pragma unroll
    for (int i = 0; i < 4; ++i)
        #pragma unroll
        for (int j = 0; j < 4; ++j) acc[i][j] = 0ull;

    #pragma unroll 8
    for (int kp = 0; kp < 32; ++kp) {
        int k2 = kp << 1;
        uint64_t bq0 = Wt2b[(tc     ) * WPAIR + kp];
        uint64_t bq1 = Wt2b[(tc + 16) * WPAIR + kp];
        uint64_t bq2 = Wt2b[(tc + 32) * WPAIR + kp];
        uint64_t bq3 = Wt2b[(tc + 48) * WPAIR + kp];
        #pragma unroll
        for (int i = 0; i < 4; ++i) {
            uint64_t a = *(const uint64_t*)(H + (tr + 16 * i) * PADK + k2);
            ffma2(acc[i][0], a, bq0);
            ffma2(acc[i][1], a, bq1);
            ffma2(acc[i][2], a, bq2);
            ffma2(acc[i][3], a, bq3);
        }
    }

    // out = (1-BETA)*Xi + BETA*(acc + b2); b2 loaded here (outside GEMM live
    // range to keep register count <= 64)
    #pragma unroll
    for (int i = 0; i < 4; ++i) {
        int row = base + tr + 16 * i;
        if (row < NV) {
            #pragma unroll
            for (int j = 0; j < 4; ++j) {
                int c = tc + 16 * j;
                float2 p = unpack2(acc[i][j]);
                float xiv = S[(tr + 16 * i) * PADK + c];
                out[(size_t)row * DD + c] =
                    (1.f - BETA) * xiv + BETA * (p.x + p.y + __ldg(b2 + c));
            }
        }
    }
}

// ---------------------------------------------------------------------------
extern "C" void kernel_launch(void* const* d_in, const int* in_sizes, int n_in,
                              void* d_out, int out_size) {
    const float* X      = (const float*)d_in[0];
    const float* X0     = (const float*)d_in[1];
    const float* W1     = (const float*)d_in[2];
    const float* b1     = (const float*)d_in[3];
    const float* W2     = (const float*)d_in[4];
    const float* b2     = (const float*)d_in[5];
    const int*   vertex = (const int*)d_in[6];
    const int*   edges  = (const int*)d_in[7];
    float*       out    = (float*)d_out;

    const int nnz = in_sizes[6];
    const int n4  = (nnz + 3) / 4;

    zero_cur<<<(NE + 255) / 256, 256>>>();
    fill_e<<<(n4 + 511) / 512, 512>>>(vertex, edges, nnz);
    fused_edge_pass<<<(NE * 16 + 255) / 256, 256>>>(X);
    epilogue<<<(NV + MTILE - 1) / MTILE, 256>>>(X0, W1, b1, W2, b2, out);
}